// round 7
// baseline (speedup 1.0000x reference)
#include <cuda_runtime.h>
#include <math.h>
#include <stdint.h>

// ---------------- problem constants ----------------
#define T_STEPS 64
#define B_      32
#define D_      1024
#define L_      2
#define MEM_    35
#define NTOK_   32000
#define HEADS_  2
#define DK_     512
#define BD      (B_*D_)            // 32768
#define MB      (MEM_*B_)          // 1120
#define EPS_    1e-6f
#define SCALE_  0.04419417382415922f  // 1/sqrt(512)
#define GRID    128

// output offsets (floats): decoded, h, c, H, C
#define OFF_h   ((size_t)T_STEPS*B_*NTOK_)
#define OFF_c   (OFF_h + (size_t)L_*BD)
#define OFF_H   (OFF_c + (size_t)L_*BD)
#define OFF_C   (OFF_H + (size_t)L_*MEM_*BD)

// ---------------- device scratch ----------------
__device__ float g_e[BD];
__device__ float g_eln[BD];
__device__ float g_q[BD];
__device__ float g_scores[HEADS_*B_*MB];
__device__ float g_attnw[HEADS_*B_*MB];
__device__ float g_att[BD];
__device__ float g_ha[BD];            // e + bo + att@Wo  (h_att accumulator)
__device__ float g_gates[B_*4*D_];    // LSTM layer0 gates
__device__ float g_gates2[B_*4*D_];   // LSTM layer1 gates
__device__ float g_h[L_*BD];
__device__ float g_c[L_*BD];
__device__ float g_KC[MEM_*BD];
__device__ float g_VC[MEM_*BD];
__device__ float g_X[T_STEPS*BD];
__device__ float g_histh[T_STEPS*L_*BD];
__device__ float g_histc[T_STEPS*L_*BD];

__device__ unsigned g_bc;   // barrier arrive counter (self-resets each launch)
__device__ unsigned g_be;   // barrier epoch (monotonic across launches)

// ---------------- f32x2 helpers ----------------
__device__ __forceinline__ void fma2(unsigned long long &c, unsigned long long a,
                                     unsigned long long b) {
    asm("fma.rn.f32x2 %0, %1, %2, %0;" : "+l"(c) : "l"(a), "l"(b));
}
__device__ __forceinline__ float2 unpk(unsigned long long v) {
    float2 f;
    asm("mov.b64 {%0,%1}, %2;" : "=f"(f.x), "=f"(f.y) : "l"(v));
    return f;
}
__device__ __forceinline__ float sigf(float x) { return 1.f/(1.f+expf(-x)); }

// ---------------- grid barrier (epoch-based, replay-safe) ----------------
__device__ __forceinline__ void gbar(unsigned target) {
    __syncthreads();
    if (threadIdx.x == 0) {
        __threadfence();
        unsigned a = atomicAdd(&g_bc, 1);
        if (a == GRID - 1) {
            g_bc = 0;
            __threadfence();
            atomicAdd(&g_be, 1);
        } else {
            while (*(volatile unsigned*)&g_be != target) __nanosleep(64);
        }
        __threadfence();
    }
    __syncthreads();
}

// ---------------- shared memory ----------------
struct __align__(16) SMg { float As[32*68]; float Bs[32*132]; };
union SMU { SMg g; float red[256]; };

// ======================================================================
// 32(m) x 128(n) output tile over k-range [k0,k1) (multiple of 32).
// blayn=false: += A[m,k] * W[wn0+n, k]   (W row-major [N,K], rows guarded by Nw)
// blayn=true : += A[m,k] * W[k, wn0+n]   (W row-major [K,N], assumed in-range)
// A2 (optional) is added elementwise to A while staging (for hin = ha + h).
// atomic=true: atomicAdd into outp (cols guarded by Nw)
// atomic=false: direct store with bias (no guards; tiles must be exact)
// Thread map: lane&7 -> 4 m rows; warp*16 + (lane>>3)*4 -> 4 n cols.
// Inner loop: 2 broadcast LDS.128 (dup A) + 1 LDS.128 (B) + 8 FFMA2.
// Software pipeline: registers prefetch chunk c+1 during compute of chunk c.
// ======================================================================
__device__ void tile_mm(
    const float* __restrict__ A, const float* __restrict__ A2, int lda,
    const float* __restrict__ W, int ldw, bool blayn, int wn0, int Nw,
    int k0, int k1, float* __restrict__ outp, int ldo,
    const float* __restrict__ bias, bool atomic, SMg* sm)
{
    const int t    = threadIdx.x;
    const int lane = t & 31, w = t >> 5;
    const int mA   = t >> 3;          // staging A row 0..31
    const int kA   = (t & 7) * 4;     // staging k sub-offset 0..28
    const int mb   = (lane & 7) * 8;  // As dup float base
    const int nloc = w*16 + (lane >> 3)*4;

    unsigned long long acc[4][2];
#pragma unroll
    for (int i = 0; i < 4; i++) { acc[i][0] = 0ull; acc[i][1] = 0ull; }

    const int nch = (k1 - k0) >> 5;
    float4 va; float4 vw[4];

#define LOAD_CHUNK(c) do {                                                      \
        const int kc_ = k0 + (c)*32;                                            \
        va = *(const float4*)(A + (size_t)mA*lda + kc_ + kA);                   \
        if (A2) {                                                               \
            float4 v2_ = *(const float4*)(A2 + (size_t)mA*lda + kc_ + kA);      \
            va.x += v2_.x; va.y += v2_.y; va.z += v2_.z; va.w += v2_.w;         \
        }                                                                       \
        if (!blayn) {                                                           \
            _Pragma("unroll")                                                   \
            for (int r = 0; r < 4; r++) {                                       \
                int row_ = r*32 + (t >> 3);                                     \
                if (wn0 + row_ < Nw)                                            \
                    vw[r] = *(const float4*)(W + (size_t)(wn0+row_)*ldw + kc_ + kA); \
                else vw[r] = make_float4(0.f,0.f,0.f,0.f);                      \
            }                                                                   \
        } else {                                                                \
            _Pragma("unroll")                                                   \
            for (int j = 0; j < 4; j++) {                                       \
                int k_ = (t >> 5)*4 + j;                                        \
                vw[j] = *(const float4*)(W + (size_t)(kc_ + k_)*ldw + wn0 + (t&31)*4); \
            }                                                                   \
        }                                                                       \
    } while (0)

    LOAD_CHUNK(0);
    for (int c = 0; c < nch; c++) {
        __syncthreads();
        // store staged chunk to smem (A duplicated along m)
#pragma unroll
        for (int j = 0; j < 4; j++) {
            float v = (&va.x)[j];
            sm->As[(kA+j)*68 + 2*mA]     = v;
            sm->As[(kA+j)*68 + 2*mA + 1] = v;
        }
        if (!blayn) {
#pragma unroll
            for (int r = 0; r < 4; r++) {
                int row = r*32 + (t >> 3);
#pragma unroll
                for (int j = 0; j < 4; j++)
                    sm->Bs[(kA+j)*132 + row] = (&vw[r].x)[j];
            }
        } else {
#pragma unroll
            for (int j = 0; j < 4; j++) {
                int k = (t >> 5)*4 + j;
                *(float4*)&sm->Bs[k*132 + (t&31)*4] = vw[j];
            }
        }
        __syncthreads();
        if (c + 1 < nch) LOAD_CHUNK(c + 1);
        // compute 32 k
#pragma unroll
        for (int kk = 0; kk < 32; kk++) {
            const ulonglong2 aa0 = *(const ulonglong2*)&sm->As[kk*68 + mb];
            const ulonglong2 aa1 = *(const ulonglong2*)&sm->As[kk*68 + mb + 4];
            const ulonglong2 bb  = *(const ulonglong2*)&sm->Bs[kk*132 + nloc];
            fma2(acc[0][0], aa0.x, bb.x); fma2(acc[0][1], aa0.x, bb.y);
            fma2(acc[1][0], aa0.y, bb.x); fma2(acc[1][1], aa0.y, bb.y);
            fma2(acc[2][0], aa1.x, bb.x); fma2(acc[2][1], aa1.x, bb.y);
            fma2(acc[3][0], aa1.y, bb.x); fma2(acc[3][1], aa1.y, bb.y);
        }
    }
#undef LOAD_CHUNK
    // epilogue
    const int m0 = (lane & 7) * 4;
#pragma unroll
    for (int i = 0; i < 4; i++) {
        int m = m0 + i;
#pragma unroll
        for (int j = 0; j < 2; j++) {
            float2 v = unpk(acc[i][j]);
            int n = wn0 + nloc + 2*j;
            if (atomic) {
                if (n   < Nw) atomicAdd(&outp[(size_t)m*ldo + n],   v.x);
                if (n+1 < Nw) atomicAdd(&outp[(size_t)m*ldo + n+1], v.y);
            } else {
                outp[(size_t)m*ldo + n]   = v.x + bias[n];
                outp[(size_t)m*ldo + n+1] = v.y + bias[n+1];
            }
        }
    }
}

// ---------------- standalone GEMM (KV init + batched decode) ----------------
__global__ void __launch_bounds__(256) gemm_std(
    const float* __restrict__ A, const float* __restrict__ W,
    const float* __restrict__ bias, float* __restrict__ out,
    int lda, int ldw, int ldo, int K)
{
    __shared__ SMg sm;
    tile_mm(A + (size_t)blockIdx.y*32*lda, nullptr, lda,
            W, ldw, false, blockIdx.x*128, 1 << 30,
            0, K, out + (size_t)blockIdx.y*32*ldo, ldo, bias, false, &sm);
}

// ---------------- persistent 64-step kernel ----------------
__global__ void __launch_bounds__(256, 1) step_all_k(
    const int* __restrict__ tokens, const float* __restrict__ emb,
    const float* __restrict__ lg, const float* __restrict__ lb,
    const float* __restrict__ Wq, const float* __restrict__ bq,
    const float* __restrict__ Wk, const float* __restrict__ bk,
    const float* __restrict__ Wv, const float* __restrict__ bv,
    const float* __restrict__ Wo, const float* __restrict__ bo,
    const float* __restrict__ W_ih, const float* __restrict__ b_ih,
    const float* __restrict__ W_hh, const float* __restrict__ b_hh)
{
    __shared__ SMU smu;
    SMg* sm = &smu.g;
    const int bid = blockIdx.x, tid = threadIdx.x;

    const unsigned ebase = *(volatile unsigned*)&g_be;
    unsigned nb_ = 0;
#define GB() do { nb_++; gbar(ebase + nb_); } while (0)

    for (int t = 0; t < T_STEPS; t++) {
        const int slot = t % MEM_;
        // ======== P1: embed+LN (0-31) | q=bq (32-63) | scores=0 (64-95) | att=0 (96-127)
        if (bid < 32) {
            const int b = bid;
            const int tok = tokens[t*B_ + b];
            const float* __restrict__ row = emb + (size_t)tok * D_;
            float v[4]; float s = 0.f;
#pragma unroll
            for (int i = 0; i < 4; i++) { v[i] = row[tid + i*256]; s += v[i]; }
            smu.red[tid] = s; __syncthreads();
            for (int o = 128; o > 0; o >>= 1) { if (tid < o) smu.red[tid] += smu.red[tid+o]; __syncthreads(); }
            const float mu = smu.red[0] * (1.f/D_);
            __syncthreads();
            s = 0.f;
#pragma unroll
            for (int i = 0; i < 4; i++) { float d = v[i]-mu; s += d*d; }
            smu.red[tid] = s; __syncthreads();
            for (int o = 128; o > 0; o >>= 1) { if (tid < o) smu.red[tid] += smu.red[tid+o]; __syncthreads(); }
            const float inv = 1.f / (sqrtf(smu.red[0] / (float)(D_-1)) + EPS_);
            __syncthreads();
#pragma unroll
            for (int i = 0; i < 4; i++) {
                int d = tid + i*256;
                g_e[(size_t)b*D_ + d] = v[i];
                g_eln[(size_t)b*D_ + d] = lg[d]*(v[i]-mu)*inv + lb[d];
            }
        } else if (bid < 64) {
            int base = (bid-32)*256 + tid;
#pragma unroll
            for (int s = 0; s < 4; s++) { int i = base + s*8192; g_q[i] = bq[i & 1023]; }
        } else if (bid < 96) {
            int base = (bid-64)*256 + tid;
            for (int s = 0; s < 9; s++) { int i = base + s*8192; if (i < HEADS_*B_*MB) g_scores[i] = 0.f; }
        } else {
            int base = (bid-96)*256 + tid;
#pragma unroll
            for (int s = 0; s < 4; s++) { int i = base + s*8192; g_att[i] = 0.f; }
        }
        GB();
        // ======== P2: q jobs (0-31) | g_ha = e + bo (32-63)
        if (bid < 32) {
            int tile = bid & 7, split = bid >> 3;
            tile_mm(g_eln, nullptr, D_, Wq, D_, false, tile*128, D_,
                    split*256, split*256+256, g_q, D_, nullptr, true, sm);
        } else if (bid < 64) {
            int base = (bid-32)*256 + tid;
#pragma unroll
            for (int s = 0; s < 4; s++) { int i = base + s*8192; g_ha[i] = g_e[i] + bo[i & 1023]; }
        }
        GB();
        // ======== P3: scores jobs (36): scores[h][b][m] += q_h[b,:] . KC_h[m,:]
        if (bid < 36) {
            int tile = bid % 9, rest = bid / 9;
            int h = rest >> 1, split = rest & 1;
            tile_mm(g_q + h*DK_, nullptr, D_, g_KC + h*DK_, D_, false, tile*128, MB,
                    split*256, split*256+256,
                    g_scores + (size_t)h*B_*MB, MB, nullptr, true, sm);
        }
        GB();
        // ======== P4: softmax over memory (64 rows)
        if (bid < HEADS_*B_) {
            const float* __restrict__ s = g_scores + (size_t)bid * MB;
            float* __restrict__ w = g_attnw + (size_t)bid * MB;
            float mx = -1e30f;
            for (int i = tid; i < MB; i += 256) mx = fmaxf(mx, s[i]);
            smu.red[tid] = mx; __syncthreads();
            for (int o = 128; o > 0; o >>= 1) { if (tid < o) smu.red[tid] = fmaxf(smu.red[tid], smu.red[tid+o]); __syncthreads(); }
            const float m2 = smu.red[0] * SCALE_;
            __syncthreads();
            float sum = 0.f;
            for (int i = tid; i < MB; i += 256) { float e = expf(fmaf(s[i], SCALE_, -m2)); w[i] = e; sum += e; }
            smu.red[tid] = sum; __syncthreads();
            for (int o = 128; o > 0; o >>= 1) { if (tid < o) smu.red[tid] += smu.red[tid+o]; __syncthreads(); }
            const float inv = 1.f / smu.red[0];
            __syncthreads();
            for (int i = tid; i < MB; i += 256) w[i] *= inv;
        }
        GB();
        // ======== P5: att jobs (32): att[b, h*DK+n] += attnw_h[b,:] . VC[:, h*DK+n]
        if (bid < 32) {
            static const int kr[5] = {0, 288, 576, 864, 1120};
            int h = bid >> 4, r = bid & 15;
            int tile = r & 3, split = r >> 2;
            tile_mm(g_attnw + (size_t)h*B_*MB, nullptr, MB, g_VC + h*DK_, D_, true,
                    tile*128, DK_, kr[split], kr[split+1],
                    g_att + h*DK_, D_, nullptr, true, sm);
        }
        GB();
        // ======== P6: o jobs (0-31) into g_ha | gates0 = bias (64-95)
        if (bid < 32) {
            int tile = bid & 7, split = bid >> 3;
            tile_mm(g_att, nullptr, D_, Wo, D_, false, tile*128, D_,
                    split*256, split*256+256, g_ha, D_, nullptr, true, sm);
        } else if (bid >= 64 && bid < 96) {
            int base = (bid-64)*256 + tid;
#pragma unroll
            for (int s = 0; s < 16; s++) {
                int i = base + s*8192;
                g_gates[i] = b_ih[i & 4095] + b_hh[i & 4095];
            }
        }
        GB();
        // ======== P7: gates L0 jobs (128): e@Wih0^T + (ha+h0)@Whh0^T
        {
            int tile = bid & 31, split = bid >> 5;
            if (split < 2)
                tile_mm(g_e, nullptr, D_, W_ih, D_, false, tile*128, 4*D_,
                        split*512, split*512+512, g_gates, 4*D_, nullptr, true, sm);
            else
                tile_mm(g_ha, g_h, D_, W_hh, D_, false, tile*128, 4*D_,
                        (split-2)*512, (split-2)*512+512, g_gates, 4*D_, nullptr, true, sm);
        }
        GB();
        // ======== P8: pointwise L0 + init gates2 bias + init KV slot bias
        {
            const int idx = bid*256 + tid;
            const int b = idx >> 10, d = idx & 1023;
            const float* __restrict__ gr = g_gates + (size_t)b*4*D_;
            const float ig = gr[d], fg = gr[D_+d], gg = gr[2*D_+d], og = gr[3*D_+d];
            const float cn = sigf(fg)*g_c[idx] + sigf(ig)*tanhf(gg);
            const float hn = sigf(og)*tanhf(cn);
            g_h[idx] = hn; g_c[idx] = cn;
            g_histh[((size_t)t*L_)*BD + idx] = hn;
            g_histc[((size_t)t*L_)*BD + idx] = cn;
#pragma unroll
            for (int s = 0; s < 4; s++) {
                int i = idx + s*32768;
                g_gates2[i] = b_ih[4*D_ + (i & 4095)] + b_hh[4*D_ + (i & 4095)];
            }
            g_KC[(size_t)slot*BD + idx] = bk[d];
            g_VC[(size_t)slot*BD + idx] = bv[d];
        }
        GB();
        // ======== P9: gates L1 jobs (128): h0new@Wih1^T + (ha+h1)@Whh1^T
        {
            int tile = bid & 31, split = bid >> 5;
            if (split < 2)
                tile_mm(g_h, nullptr, D_, W_ih + (size_t)4*D_*D_, D_, false, tile*128, 4*D_,
                        split*512, split*512+512, g_gates2, 4*D_, nullptr, true, sm);
            else
                tile_mm(g_ha, g_h + BD, D_, W_hh + (size_t)4*D_*D_, D_, false, tile*128, 4*D_,
                        (split-2)*512, (split-2)*512+512, g_gates2, 4*D_, nullptr, true, sm);
        }
        GB();
        // ======== P10: pointwise L1 (+X history) | KV jobs (0-31)
        {
            const int idx = bid*256 + tid;
            const int b = idx >> 10, d = idx & 1023;
            const float* __restrict__ gr = g_gates2 + (size_t)b*4*D_;
            const float ig = gr[d], fg = gr[D_+d], gg = gr[2*D_+d], og = gr[3*D_+d];
            const float cn = sigf(fg)*g_c[BD + idx] + sigf(ig)*tanhf(gg);
            const float hn = sigf(og)*tanhf(cn);
            g_h[BD + idx] = hn; g_c[BD + idx] = cn;
            g_histh[((size_t)t*L_ + 1)*BD + idx] = hn;
            g_histc[((size_t)t*L_ + 1)*BD + idx] = cn;
            g_X[(size_t)t*BD + idx] = hn;
        }
        __syncthreads();
        if (bid < 32) {
            bool isK = bid < 16;
            int r = bid & 15, tile = r & 7, split = r >> 3;
            tile_mm(g_h, nullptr, D_, isK ? Wk : Wv, D_, false, tile*128, D_,
                    split*512, split*512+512,
                    (isK ? g_KC : g_VC) + (size_t)slot*BD, D_, nullptr, true, sm);
        }
        GB();
    }
#undef GB
}

// ---------------- final state / memory gather ----------------
__global__ void __launch_bounds__(256) finalize_k(float* __restrict__ out)
{
    const int idx = blockIdx.x*256 + threadIdx.x;
    const int l = idx / (MEM_*BD);
    const int r = idx % (MEM_*BD);
    const int m = r / BD, j = r % BD;
    const size_t src = ((size_t)(T_STEPS - MEM_ + m)*L_ + l)*BD + j;
    out[OFF_H + idx] = g_histh[src];
    out[OFF_C + idx] = g_histc[src];
    if (idx < L_*BD) {
        out[OFF_h + idx] = g_h[idx];
        out[OFF_c + idx] = g_c[idx];
    }
}

// ---------------- host ----------------
extern "C" void kernel_launch(void* const* d_in, const int* in_sizes, int n_in,
                              void* d_out, int out_size)
{
    const int*   tokens = (const int*)  d_in[0];
    const float* emb    = (const float*)d_in[1];
    const float* ln_g   = (const float*)d_in[2];
    const float* ln_b   = (const float*)d_in[3];
    const float* Wq     = (const float*)d_in[4];
    const float* bq     = (const float*)d_in[5];
    const float* Wk     = (const float*)d_in[6];
    const float* bk     = (const float*)d_in[7];
    const float* Wv     = (const float*)d_in[8];
    const float* bv     = (const float*)d_in[9];
    const float* Wo     = (const float*)d_in[10];
    const float* bo     = (const float*)d_in[11];
    const float* W_ih   = (const float*)d_in[12];
    const float* b_ih   = (const float*)d_in[13];
    const float* W_hh   = (const float*)d_in[14];
    const float* b_hh   = (const float*)d_in[15];
    const float* dec_W  = (const float*)d_in[16];
    const float* dec_b  = (const float*)d_in[17];
    const float* h0     = (const float*)d_in[18];
    const float* c0     = (const float*)d_in[19];
    const float* H0     = (const float*)d_in[20];
    // d_in[21] = C0: unobservable (T >= MEM rolls it out)
    float* out = (float*)d_out;

    float *ph, *pc, *pKC, *pVC, *pX;
    cudaGetSymbolAddress((void**)&ph,  g_h);
    cudaGetSymbolAddress((void**)&pc,  g_c);
    cudaGetSymbolAddress((void**)&pKC, g_KC);
    cudaGetSymbolAddress((void**)&pVC, g_VC);
    cudaGetSymbolAddress((void**)&pX,  g_X);

    cudaMemcpyAsync(ph, h0, (size_t)L_*BD*sizeof(float), cudaMemcpyDeviceToDevice);
    cudaMemcpyAsync(pc, c0, (size_t)L_*BD*sizeof(float), cudaMemcpyDeviceToDevice);

    // initial K/V cache from H0 layer 0: rows m*B+b of [MEM*B, D]
    gemm_std<<<dim3(8, 35), 256>>>(H0, Wk, bk, pKC, D_, D_, D_, D_);
    gemm_std<<<dim3(8, 35), 256>>>(H0, Wv, bv, pVC, D_, D_, D_, D_);

    // persistent 64-step kernel
    step_all_k<<<GRID, 256>>>(tokens, emb, ln_g, ln_b, Wq, bq, Wk, bk, Wv, bv,
                              Wo, bo, W_ih, b_ih, W_hh, b_hh);

    // batched decode: [2048, 32000] = X @ dec_W^T + dec_b
    gemm_std<<<dim3(NTOK_/128, T_STEPS*B_/32), 256>>>(pX, dec_W, dec_b, out,
                                                      D_, D_, NTOK_, D_);

    finalize_k<<<(L_*MEM_*BD)/256, 256>>>(out);
}

// round 14
// speedup vs baseline: 1.4273x; 1.4273x over previous
#include <cuda_runtime.h>
#include <math.h>
#include <stdint.h>

// ---------------- problem constants ----------------
#define T_STEPS 64
#define B_      32
#define D_      1024
#define L_      2
#define MEM_    35
#define NTOK_   32000
#define HEADS_  2
#define DK_     512
#define BD      (B_*D_)            // 32768
#define MB      (MEM_*B_)          // 1120
#define EPS_    1e-6f
#define SCALE_  0.04419417382415922f  // 1/sqrt(512)
#define GRID    128

// output offsets (floats): decoded, h, c, H, C
#define OFF_h   ((size_t)T_STEPS*B_*NTOK_)
#define OFF_c   (OFF_h + (size_t)L_*BD)
#define OFF_H   (OFF_c + (size_t)L_*BD)
#define OFF_C   (OFF_H + (size_t)L_*MEM_*BD)

// ---------------- device scratch ----------------
__device__ float g_e[BD];
__device__ float g_eln[BD];
__device__ float g_q[BD];
__device__ float g_scores[HEADS_*B_*MB];
__device__ float g_attnw[HEADS_*B_*MB];
__device__ float g_att[BD];
__device__ float g_ha[BD];            // e + bo + att@Wo  (h_att accumulator)
__device__ float g_gates[B_*4*D_];    // LSTM layer0 gates
__device__ float g_gates2[B_*4*D_];   // LSTM layer1 gates
__device__ float g_h[L_*BD];
__device__ float g_c[L_*BD];
__device__ float g_KC[MEM_*BD];
__device__ float g_VC[MEM_*BD];
__device__ float g_X[T_STEPS*BD];
__device__ float g_histh[T_STEPS*L_*BD];
__device__ float g_histc[T_STEPS*L_*BD];

__device__ unsigned g_bc;   // barrier arrive counter (self-resets each launch)
__device__ unsigned g_be;   // barrier epoch (monotonic across launches)

// ---------------- f32x2 helpers ----------------
__device__ __forceinline__ void fma2(unsigned long long &c, unsigned long long a,
                                     unsigned long long b) {
    asm("fma.rn.f32x2 %0, %1, %2, %0;" : "+l"(c) : "l"(a), "l"(b));
}
__device__ __forceinline__ float2 unpk(unsigned long long v) {
    float2 f;
    asm("mov.b64 {%0,%1}, %2;" : "=f"(f.x), "=f"(f.y) : "l"(v));
    return f;
}
__device__ __forceinline__ float sigf(float x) { return 1.f/(1.f+expf(-x)); }

// ---------------- grid barrier (epoch-based, replay-safe) ----------------
__device__ __forceinline__ void gbar(unsigned target) {
    __syncthreads();
    if (threadIdx.x == 0) {
        __threadfence();
        unsigned a = atomicAdd(&g_bc, 1);
        if (a == GRID - 1) {
            g_bc = 0;
            __threadfence();
            atomicAdd(&g_be, 1);
        } else {
            while (*(volatile unsigned*)&g_be != target) __nanosleep(64);
        }
        __threadfence();
    }
    __syncthreads();
}

// ---------------- shared memory ----------------
struct __align__(16) SMg { float As[32*68]; float Bs[32*132]; };
union SMU { SMg g; float red[256]; };

// Skewed offset for dup'd-A group g (g=0..7): the 16B words across groups
// tile all 32 banks exactly once -> conflict-free broadcast LDS.128.
__device__ __forceinline__ int skoff(int g) { return g*8 + (g & 4); }

// ======================================================================
// 32(m) x 128(n) output tile over k-range [k0,k1) (multiple of 32).
// blayn=false: += A[m,k] * W[wn0+n, k]   (W row-major [N,K], rows guarded by Nw)
// blayn=true : += A[m,k] * W[k, wn0+n]   (W row-major [K,N], assumed in-range)
// A2 (optional) is added elementwise to A while staging (for hin = ha + h).
// atomic=true: atomicAdd into outp (cols guarded by Nw)
// atomic=false: direct store with bias (no guards; tiles must be exact)
// Thread map: lane&7 -> 4 m rows; warp*16 + (lane>>3)*4 -> 4 n cols.
// Inner loop: 2 broadcast LDS.128 (skew-dup A, conflict-free) + 1 LDS.128 (B)
// + 8 FFMA2. Register prefetch of chunk c+1 during compute of chunk c.
// ======================================================================
__device__ void tile_mm(
    const float* __restrict__ A, const float* __restrict__ A2, int lda,
    const float* __restrict__ W, int ldw, bool blayn, int wn0, int Nw,
    int k0, int k1, float* __restrict__ outp, int ldo,
    const float* __restrict__ bias, bool atomic, SMg* sm)
{
    const int t    = threadIdx.x;
    const int lane = t & 31, w = t >> 5;
    const int mA   = t >> 3;          // staging A row 0..31
    const int kA   = (t & 7) * 4;     // staging k sub-offset 0..28
    const int mb   = skoff(lane & 7); // skewed dup-A float base
    const int abase = skoff(mA >> 2) + 2*(mA & 3);  // staging write base
    const int nloc = w*16 + (lane >> 3)*4;

    unsigned long long acc[4][2];
#pragma unroll
    for (int i = 0; i < 4; i++) { acc[i][0] = 0ull; acc[i][1] = 0ull; }

    const int nch = (k1 - k0) >> 5;
    float4 va; float4 vw[4];

#define LOAD_CHUNK(c) do {                                                      \
        const int kc_ = k0 + (c)*32;                                            \
        va = *(const float4*)(A + (size_t)mA*lda + kc_ + kA);                   \
        if (A2) {                                                               \
            float4 v2_ = *(const float4*)(A2 + (size_t)mA*lda + kc_ + kA);      \
            va.x += v2_.x; va.y += v2_.y; va.z += v2_.z; va.w += v2_.w;         \
        }                                                                       \
        if (!blayn) {                                                           \
            _Pragma("unroll")                                                   \
            for (int r = 0; r < 4; r++) {                                       \
                int row_ = r*32 + (t >> 3);                                     \
                if (wn0 + row_ < Nw)                                            \
                    vw[r] = *(const float4*)(W + (size_t)(wn0+row_)*ldw + kc_ + kA); \
                else vw[r] = make_float4(0.f,0.f,0.f,0.f);                      \
            }                                                                   \
        } else {                                                                \
            _Pragma("unroll")                                                   \
            for (int j = 0; j < 4; j++) {                                       \
                int k_ = (t >> 5)*4 + j;                                        \
                vw[j] = *(const float4*)(W + (size_t)(kc_ + k_)*ldw + wn0 + (t&31)*4); \
            }                                                                   \
        }                                                                       \
    } while (0)

    LOAD_CHUNK(0);
    for (int c = 0; c < nch; c++) {
        __syncthreads();
        // store staged chunk to smem (A duplicated along m, skewed layout)
#pragma unroll
        for (int j = 0; j < 4; j++) {
            float v = (&va.x)[j];
            sm->As[(kA+j)*68 + abase]     = v;
            sm->As[(kA+j)*68 + abase + 1] = v;
        }
        if (!blayn) {
#pragma unroll
            for (int r = 0; r < 4; r++) {
                int row = r*32 + (t >> 3);
#pragma unroll
                for (int j = 0; j < 4; j++)
                    sm->Bs[(kA+j)*132 + row] = (&vw[r].x)[j];
            }
        } else {
#pragma unroll
            for (int j = 0; j < 4; j++) {
                int k = (t >> 5)*4 + j;
                *(float4*)&sm->Bs[k*132 + (t&31)*4] = vw[j];
            }
        }
        __syncthreads();
        if (c + 1 < nch) LOAD_CHUNK(c + 1);
        // compute 32 k
#pragma unroll
        for (int kk = 0; kk < 32; kk++) {
            const ulonglong2 aa0 = *(const ulonglong2*)&sm->As[kk*68 + mb];
            const ulonglong2 aa1 = *(const ulonglong2*)&sm->As[kk*68 + mb + 4];
            const ulonglong2 bb  = *(const ulonglong2*)&sm->Bs[kk*132 + nloc];
            fma2(acc[0][0], aa0.x, bb.x); fma2(acc[0][1], aa0.x, bb.y);
            fma2(acc[1][0], aa0.y, bb.x); fma2(acc[1][1], aa0.y, bb.y);
            fma2(acc[2][0], aa1.x, bb.x); fma2(acc[2][1], aa1.x, bb.y);
            fma2(acc[3][0], aa1.y, bb.x); fma2(acc[3][1], aa1.y, bb.y);
        }
    }
#undef LOAD_CHUNK
    // epilogue
    const int m0 = (lane & 7) * 4;
#pragma unroll
    for (int i = 0; i < 4; i++) {
        int m = m0 + i;
#pragma unroll
        for (int j = 0; j < 2; j++) {
            float2 v = unpk(acc[i][j]);
            int n = wn0 + nloc + 2*j;
            if (atomic) {
                if (n   < Nw) atomicAdd(&outp[(size_t)m*ldo + n],   v.x);
                if (n+1 < Nw) atomicAdd(&outp[(size_t)m*ldo + n+1], v.y);
            } else {
                outp[(size_t)m*ldo + n]   = v.x + bias[n];
                outp[(size_t)m*ldo + n+1] = v.y + bias[n+1];
            }
        }
    }
}

// ---------------- standalone GEMM (KV init + batched decode) ----------------
__global__ void __launch_bounds__(256) gemm_std(
    const float* __restrict__ A, const float* __restrict__ W,
    const float* __restrict__ bias, float* __restrict__ out,
    int lda, int ldw, int ldo, int K)
{
    __shared__ SMg sm;
    tile_mm(A + (size_t)blockIdx.y*32*lda, nullptr, lda,
            W, ldw, false, blockIdx.x*128, 1 << 30,
            0, K, out + (size_t)blockIdx.y*32*ldo, ldo, bias, false, &sm);
}

// ---------------- persistent 64-step kernel ----------------
__global__ void __launch_bounds__(256, 1) step_all_k(
    const int* __restrict__ tokens, const float* __restrict__ emb,
    const float* __restrict__ lg, const float* __restrict__ lb,
    const float* __restrict__ Wq, const float* __restrict__ bq,
    const float* __restrict__ Wk, const float* __restrict__ bk,
    const float* __restrict__ Wv, const float* __restrict__ bv,
    const float* __restrict__ Wo, const float* __restrict__ bo,
    const float* __restrict__ W_ih, const float* __restrict__ b_ih,
    const float* __restrict__ W_hh, const float* __restrict__ b_hh)
{
    __shared__ SMU smu;
    SMg* sm = &smu.g;
    const int bid = blockIdx.x, tid = threadIdx.x;

    const unsigned ebase = *(volatile unsigned*)&g_be;
    unsigned nb_ = 0;
#define GB() do { nb_++; gbar(ebase + nb_); } while (0)

    for (int t = 0; t < T_STEPS; t++) {
        const int slot = t % MEM_;
        // ======== P1: embed+LN (0-31) | q=bq (32-63) | scores=0 (64-95) | att=0 (96-127)
        if (bid < 32) {
            const int b = bid;
            const int tok = tokens[t*B_ + b];
            const float* __restrict__ row = emb + (size_t)tok * D_;
            float v[4]; float s = 0.f;
#pragma unroll
            for (int i = 0; i < 4; i++) { v[i] = row[tid + i*256]; s += v[i]; }
            smu.red[tid] = s; __syncthreads();
            for (int o = 128; o > 0; o >>= 1) { if (tid < o) smu.red[tid] += smu.red[tid+o]; __syncthreads(); }
            const float mu = smu.red[0] * (1.f/D_);
            __syncthreads();
            s = 0.f;
#pragma unroll
            for (int i = 0; i < 4; i++) { float d = v[i]-mu; s += d*d; }
            smu.red[tid] = s; __syncthreads();
            for (int o = 128; o > 0; o >>= 1) { if (tid < o) smu.red[tid] += smu.red[tid+o]; __syncthreads(); }
            const float inv = 1.f / (sqrtf(smu.red[0] / (float)(D_-1)) + EPS_);
            __syncthreads();
#pragma unroll
            for (int i = 0; i < 4; i++) {
                int d = tid + i*256;
                g_e[(size_t)b*D_ + d] = v[i];
                g_eln[(size_t)b*D_ + d] = lg[d]*(v[i]-mu)*inv + lb[d];
            }
        } else if (bid < 64) {
            int base = (bid-32)*256 + tid;
#pragma unroll
            for (int s = 0; s < 4; s++) { int i = base + s*8192; g_q[i] = bq[i & 1023]; }
        } else if (bid < 96) {
            int base = (bid-64)*256 + tid;
            for (int s = 0; s < 9; s++) { int i = base + s*8192; if (i < HEADS_*B_*MB) g_scores[i] = 0.f; }
        } else {
            int base = (bid-96)*256 + tid;
#pragma unroll
            for (int s = 0; s < 4; s++) { int i = base + s*8192; g_att[i] = 0.f; }
        }
        GB();
        // ======== P2: q jobs (0-31) | g_ha = e + bo (32-63)
        if (bid < 32) {
            int tile = bid & 7, split = bid >> 3;
            tile_mm(g_eln, nullptr, D_, Wq, D_, false, tile*128, D_,
                    split*256, split*256+256, g_q, D_, nullptr, true, sm);
        } else if (bid < 64) {
            int base = (bid-32)*256 + tid;
#pragma unroll
            for (int s = 0; s < 4; s++) { int i = base + s*8192; g_ha[i] = g_e[i] + bo[i & 1023]; }
        }
        GB();
        // ======== P3: scores jobs (36): scores[h][b][m] += q_h[b,:] . KC_h[m,:]
        if (bid < 36) {
            int tile = bid % 9, rest = bid / 9;
            int h = rest >> 1, split = rest & 1;
            tile_mm(g_q + h*DK_, nullptr, D_, g_KC + h*DK_, D_, false, tile*128, MB,
                    split*256, split*256+256,
                    g_scores + (size_t)h*B_*MB, MB, nullptr, true, sm);
        }
        GB();
        // ======== P4: softmax over memory (64 rows)
        if (bid < HEADS_*B_) {
            const float* __restrict__ s = g_scores + (size_t)bid * MB;
            float* __restrict__ w = g_attnw + (size_t)bid * MB;
            float mx = -1e30f;
            for (int i = tid; i < MB; i += 256) mx = fmaxf(mx, s[i]);
            smu.red[tid] = mx; __syncthreads();
            for (int o = 128; o > 0; o >>= 1) { if (tid < o) smu.red[tid] = fmaxf(smu.red[tid], smu.red[tid+o]); __syncthreads(); }
            const float m2 = smu.red[0] * SCALE_;
            __syncthreads();
            float sum = 0.f;
            for (int i = tid; i < MB; i += 256) { float e = expf(fmaf(s[i], SCALE_, -m2)); w[i] = e; sum += e; }
            smu.red[tid] = sum; __syncthreads();
            for (int o = 128; o > 0; o >>= 1) { if (tid < o) smu.red[tid] += smu.red[tid+o]; __syncthreads(); }
            const float inv = 1.f / smu.red[0];
            __syncthreads();
            for (int i = tid; i < MB; i += 256) w[i] *= inv;
        }
        GB();
        // ======== P5: att jobs (32): att[b, h*DK+n] += attnw_h[b,:] . VC[:, h*DK+n]
        if (bid < 32) {
            static const int kr[5] = {0, 288, 576, 864, 1120};
            int h = bid >> 4, r = bid & 15;
            int tile = r & 3, split = r >> 2;
            tile_mm(g_attnw + (size_t)h*B_*MB, nullptr, MB, g_VC + h*DK_, D_, true,
                    tile*128, DK_, kr[split], kr[split+1],
                    g_att + h*DK_, D_, nullptr, true, sm);
        }
        GB();
        // ======== P6: o jobs (0-31) into g_ha | gates0 = bias (64-95)
        if (bid < 32) {
            int tile = bid & 7, split = bid >> 3;
            tile_mm(g_att, nullptr, D_, Wo, D_, false, tile*128, D_,
                    split*256, split*256+256, g_ha, D_, nullptr, true, sm);
        } else if (bid >= 64 && bid < 96) {
            int base = (bid-64)*256 + tid;
#pragma unroll
            for (int s = 0; s < 16; s++) {
                int i = base + s*8192;
                g_gates[i] = b_ih[i & 4095] + b_hh[i & 4095];
            }
        }
        GB();
        // ======== P7: gates L0 jobs (128): e@Wih0^T + (ha+h0)@Whh0^T
        {
            int tile = bid & 31, split = bid >> 5;
            if (split < 2)
                tile_mm(g_e, nullptr, D_, W_ih, D_, false, tile*128, 4*D_,
                        split*512, split*512+512, g_gates, 4*D_, nullptr, true, sm);
            else
                tile_mm(g_ha, g_h, D_, W_hh, D_, false, tile*128, 4*D_,
                        (split-2)*512, (split-2)*512+512, g_gates, 4*D_, nullptr, true, sm);
        }
        GB();
        // ======== P8: pointwise L0 + init gates2 bias + init KV slot bias
        {
            const int idx = bid*256 + tid;
            const int b = idx >> 10, d = idx & 1023;
            const float* __restrict__ gr = g_gates + (size_t)b*4*D_;
            const float ig = gr[d], fg = gr[D_+d], gg = gr[2*D_+d], og = gr[3*D_+d];
            const float cn = sigf(fg)*g_c[idx] + sigf(ig)*tanhf(gg);
            const float hn = sigf(og)*tanhf(cn);
            g_h[idx] = hn; g_c[idx] = cn;
            g_histh[((size_t)t*L_)*BD + idx] = hn;
            g_histc[((size_t)t*L_)*BD + idx] = cn;
#pragma unroll
            for (int s = 0; s < 4; s++) {
                int i = idx + s*32768;
                g_gates2[i] = b_ih[4*D_ + (i & 4095)] + b_hh[4*D_ + (i & 4095)];
            }
            g_KC[(size_t)slot*BD + idx] = bk[d];
            g_VC[(size_t)slot*BD + idx] = bv[d];
        }
        GB();
        // ======== P9: gates L1 jobs (128): h0new@Wih1^T + (ha+h1)@Whh1^T
        {
            int tile = bid & 31, split = bid >> 5;
            if (split < 2)
                tile_mm(g_h, nullptr, D_, W_ih + (size_t)4*D_*D_, D_, false, tile*128, 4*D_,
                        split*512, split*512+512, g_gates2, 4*D_, nullptr, true, sm);
            else
                tile_mm(g_ha, g_h + BD, D_, W_hh + (size_t)4*D_*D_, D_, false, tile*128, 4*D_,
                        (split-2)*512, (split-2)*512+512, g_gates2, 4*D_, nullptr, true, sm);
        }
        GB();
        // ======== P10: pointwise L1 (+X history) | KV jobs (0-31)
        {
            const int idx = bid*256 + tid;
            const int b = idx >> 10, d = idx & 1023;
            const float* __restrict__ gr = g_gates2 + (size_t)b*4*D_;
            const float ig = gr[d], fg = gr[D_+d], gg = gr[2*D_+d], og = gr[3*D_+d];
            const float cn = sigf(fg)*g_c[BD + idx] + sigf(ig)*tanhf(gg);
            const float hn = sigf(og)*tanhf(cn);
            g_h[BD + idx] = hn; g_c[BD + idx] = cn;
            g_histh[((size_t)t*L_ + 1)*BD + idx] = hn;
            g_histc[((size_t)t*L_ + 1)*BD + idx] = cn;
            g_X[(size_t)t*BD + idx] = hn;
        }
        __syncthreads();
        if (bid < 32) {
            bool isK = bid < 16;
            int r = bid & 15, tile = r & 7, split = r >> 3;
            tile_mm(g_h, nullptr, D_, isK ? Wk : Wv, D_, false, tile*128, D_,
                    split*512, split*512+512,
                    (isK ? g_KC : g_VC) + (size_t)slot*BD, D_, nullptr, true, sm);
        }
        GB();
    }
#undef GB
}

// ---------------- final state / memory gather ----------------
__global__ void __launch_bounds__(256) finalize_k(float* __restrict__ out)
{
    const int idx = blockIdx.x*256 + threadIdx.x;
    const int l = idx / (MEM_*BD);
    const int r = idx % (MEM_*BD);
    const int m = r / BD, j = r % BD;
    const size_t src = ((size_t)(T_STEPS - MEM_ + m)*L_ + l)*BD + j;
    out[OFF_H + idx] = g_histh[src];
    out[OFF_C + idx] = g_histc[src];
    if (idx < L_*BD) {
        out[OFF_h + idx] = g_h[idx];
        out[OFF_c + idx] = g_c[idx];
    }
}

// ---------------- host ----------------
extern "C" void kernel_launch(void* const* d_in, const int* in_sizes, int n_in,
                              void* d_out, int out_size)
{
    const int*   tokens = (const int*)  d_in[0];
    const float* emb    = (const float*)d_in[1];
    const float* ln_g   = (const float*)d_in[2];
    const float* ln_b   = (const float*)d_in[3];
    const float* Wq     = (const float*)d_in[4];
    const float* bq     = (const float*)d_in[5];
    const float* Wk     = (const float*)d_in[6];
    const float* bk     = (const float*)d_in[7];
    const float* Wv     = (const float*)d_in[8];
    const float* bv     = (const float*)d_in[9];
    const float* Wo     = (const float*)d_in[10];
    const float* bo     = (const float*)d_in[11];
    const float* W_ih   = (const float*)d_in[12];
    const float* b_ih   = (const float*)d_in[13];
    const float* W_hh   = (const float*)d_in[14];
    const float* b_hh   = (const float*)d_in[15];
    const float* dec_W  = (const float*)d_in[16];
    const float* dec_b  = (const float*)d_in[17];
    const float* h0     = (const float*)d_in[18];
    const float* c0     = (const float*)d_in[19];
    const float* H0     = (const float*)d_in[20];
    // d_in[21] = C0: unobservable (T >= MEM rolls it out)
    float* out = (float*)d_out;

    float *ph, *pc, *pKC, *pVC, *pX;
    cudaGetSymbolAddress((void**)&ph,  g_h);
    cudaGetSymbolAddress((void**)&pc,  g_c);
    cudaGetSymbolAddress((void**)&pKC, g_KC);
    cudaGetSymbolAddress((void**)&pVC, g_VC);
    cudaGetSymbolAddress((void**)&pX,  g_X);

    cudaMemcpyAsync(ph, h0, (size_t)L_*BD*sizeof(float), cudaMemcpyDeviceToDevice);
    cudaMemcpyAsync(pc, c0, (size_t)L_*BD*sizeof(float), cudaMemcpyDeviceToDevice);

    // initial K/V cache from H0 layer 0: rows m*B+b of [MEM*B, D]
    gemm_std<<<dim3(8, 35), 256>>>(H0, Wk, bk, pKC, D_, D_, D_, D_);
    gemm_std<<<dim3(8, 35), 256>>>(H0, Wv, bv, pVC, D_, D_, D_, D_);

    // persistent 64-step kernel
    step_all_k<<<GRID, 256>>>(tokens, emb, ln_g, ln_b, Wq, bq, Wk, bk, Wv, bv,
                              Wo, bo, W_ih, b_ih, W_hh, b_hh);

    // batched decode: [2048, 32000] = X @ dec_W^T + dec_b
    gemm_std<<<dim3(NTOK_/128, T_STEPS*B_/32), 256>>>(pX, dec_W, dec_b, out,
                                                      D_, D_, NTOK_, D_);

    finalize_k<<<(L_*MEM_*BD)/256, 256>>>(out);
}

// round 17
// speedup vs baseline: 1.9320x; 1.3536x over previous
#include <cuda_runtime.h>
#include <math.h>
#include <stdint.h>

// ---------------- problem constants ----------------
#define T_STEPS 64
#define B_      32
#define D_      1024
#define L_      2
#define MEM_    35
#define NTOK_   32000
#define HEADS_  2
#define DK_     512
#define BD      (B_*D_)            // 32768
#define MB      (MEM_*B_)          // 1120
#define EPS_    1e-6f
#define SCALE_  0.04419417382415922f  // 1/sqrt(512)
#define GRID    128

// output offsets (floats): decoded, h, c, H, C
#define OFF_h   ((size_t)T_STEPS*B_*NTOK_)
#define OFF_c   (OFF_h + (size_t)L_*BD)
#define OFF_H   (OFF_c + (size_t)L_*BD)
#define OFF_C   (OFF_H + (size_t)L_*MEM_*BD)

// ---------------- device scratch ----------------
__device__ float g_e[BD];
__device__ float g_eln[BD];
__device__ float g_q[BD];
__device__ float g_scores[HEADS_*B_*MB];
__device__ float g_attnw[HEADS_*B_*MB];
__device__ float g_att[BD];
__device__ float g_ha[BD];            // e + bo + att@Wo  (h_att accumulator)
__device__ float g_gates[B_*4*D_];    // LSTM layer0 gates
__device__ float g_gates2[B_*4*D_];   // LSTM layer1 gates
__device__ float g_h[L_*BD];
__device__ float g_c[L_*BD];
__device__ float g_KC[MEM_*BD];
__device__ float g_VC[MEM_*BD];
__device__ float g_X[T_STEPS*BD];
__device__ float g_histh[T_STEPS*L_*BD];
__device__ float g_histc[T_STEPS*L_*BD];

__device__ unsigned g_bc;   // barrier arrive counter (self-resets each launch)
__device__ unsigned g_be;   // barrier epoch (monotonic across launches)

// ---------------- f32x2 helpers ----------------
__device__ __forceinline__ void fma2(unsigned long long &c, unsigned long long a,
                                     unsigned long long b) {
    asm("fma.rn.f32x2 %0, %1, %2, %0;" : "+l"(c) : "l"(a), "l"(b));
}
__device__ __forceinline__ float2 unpk(unsigned long long v) {
    float2 f;
    asm("mov.b64 {%0,%1}, %2;" : "=f"(f.x), "=f"(f.y) : "l"(v));
    return f;
}
__device__ __forceinline__ unsigned long long dupf(float x) {
    unsigned long long r;
    asm("mov.b64 %0, {%1,%1};" : "=l"(r) : "f"(x));
    return r;
}
__device__ __forceinline__ float sigf(float x) { return 1.f/(1.f+expf(-x)); }

// ---------------- grid barrier (epoch-based, replay-safe) ----------------
__device__ __forceinline__ void gbar(unsigned target) {
    __syncthreads();
    if (threadIdx.x == 0) {
        __threadfence();
        unsigned a = atomicAdd(&g_bc, 1);
        if (a == GRID - 1) {
            g_bc = 0;
            __threadfence();
            atomicAdd(&g_be, 1);
        } else {
            while (*(volatile unsigned*)&g_be != target) __nanosleep(64);
        }
        __threadfence();
    }
    __syncthreads();
}

// ---------------- shared memory ----------------
// As[k][m] stride 36 (no duplication); Bs[k][n-swizzled] stride 132.
struct __align__(16) SMg { float As[32*36]; float Bs[32*132]; };
union SMU { SMg g; float red[256]; };

// ======================================================================
// 32(m) x 128(n) output tile over k-range [k0,k1) (multiple of 32).
// blayn=false: += A[m,k] * W[wn0+n, k]   (W row-major [N,K], rows guarded by Nw)
// blayn=true : += A[m,k] * W[k, wn0+n]   (W row-major [K,N], assumed in-range)
// A2 (optional) added elementwise to A while staging (hin = ha + h).
// atomic=true: atomicAdd into outp (cols guarded by Nw); else bias store.
// Bank-conflict-free staging:
//   A: thread t stages row (t&31) at k-quad (t>>5): store bank 16w+4j+mA
//      covers all 32 banks (1 wf); read LDS.128 at kk*36+4*(lane&7): 8
//      distinct quads (1 wf); dup to packed via mov.b64.
//   B: column swizzle col^4*((k>>2)&7): store banks all-32 (proven),
//      read LDS.128 stays 4 distinct quads (1 wf).
// ======================================================================
__device__ void tile_mm(
    const float* __restrict__ A, const float* __restrict__ A2, int lda,
    const float* __restrict__ W, int ldw, bool blayn, int wn0, int Nw,
    int k0, int k1, float* __restrict__ outp, int ldo,
    const float* __restrict__ bias, bool atomic, SMg* sm)
{
    const int t    = threadIdx.x;
    const int lane = t & 31, w = t >> 5;
    const int mA   = t & 31;          // A staging row
    const int kAq  = w * 4;           // A staging k base (per warp)
    const int m8   = (lane & 7) * 4;  // A read float4 base (4 m rows)
    const int nloc = w*16 + (lane >> 3)*4;

    unsigned long long acc[4][2];
#pragma unroll
    for (int i = 0; i < 4; i++) { acc[i][0] = 0ull; acc[i][1] = 0ull; }

    const int nch = (k1 - k0) >> 5;
    float4 va; float4 vw[4];

#define LOAD_CHUNK(c) do {                                                      \
        const int kc_ = k0 + (c)*32;                                            \
        va = *(const float4*)(A + (size_t)mA*lda + kc_ + kAq);                  \
        if (A2) {                                                               \
            float4 v2_ = *(const float4*)(A2 + (size_t)mA*lda + kc_ + kAq);     \
            va.x += v2_.x; va.y += v2_.y; va.z += v2_.z; va.w += v2_.w;         \
        }                                                                       \
        if (!blayn) {                                                           \
            _Pragma("unroll")                                                   \
            for (int r = 0; r < 4; r++) {                                       \
                int row_ = r*32 + (t >> 3);                                     \
                if (wn0 + row_ < Nw)                                            \
                    vw[r] = *(const float4*)(W + (size_t)(wn0+row_)*ldw + kc_ + (t&7)*4); \
                else vw[r] = make_float4(0.f,0.f,0.f,0.f);                      \
            }                                                                   \
        } else {                                                                \
            _Pragma("unroll")                                                   \
            for (int j = 0; j < 4; j++) {                                       \
                int k_ = w*4 + j;                                               \
                vw[j] = *(const float4*)(W + (size_t)(kc_ + k_)*ldw + wn0 + (t&31)*4); \
            }                                                                   \
        }                                                                       \
    } while (0)

    LOAD_CHUNK(0);
    for (int c = 0; c < nch; c++) {
        __syncthreads();
        // ---- stage A: As[k][m], k = kAq+j (conflict-free STS.32) ----
#pragma unroll
        for (int j = 0; j < 4; j++)
            sm->As[(kAq + j)*36 + mA] = (&va.x)[j];
        // ---- stage B ----
        if (!blayn) {
            // k = 4*(t&7)+j; swizzle x = 4*((k>>2)&7) = 4*(t&7)
            const int xs = (t & 7) * 4;
#pragma unroll
            for (int r = 0; r < 4; r++) {
                int row = r*32 + (t >> 3);
#pragma unroll
                for (int j = 0; j < 4; j++)
                    sm->Bs[((t&7)*4 + j)*132 + (row ^ xs)] = (&vw[r].x)[j];
            }
        } else {
            // k = w*4+j; swizzle x = 4*((k>>2)&7) = 4*w
            const int xs = w * 4;
#pragma unroll
            for (int j = 0; j < 4; j++) {
                int k = w*4 + j;
                *(float4*)&sm->Bs[k*132 + (((t&31)*4) ^ xs)] = vw[j];
            }
        }
        __syncthreads();
        if (c + 1 < nch) LOAD_CHUNK(c + 1);
        // ---- compute 32 k ----
#pragma unroll
        for (int kk = 0; kk < 32; kk++) {
            const float4 af = *(const float4*)&sm->As[kk*36 + m8];
            const ulonglong2 bb = *(const ulonglong2*)
                &sm->Bs[kk*132 + (nloc ^ ((((kk>>2)&7))<<2))];
            const unsigned long long a0 = dupf(af.x);
            const unsigned long long a1 = dupf(af.y);
            const unsigned long long a2 = dupf(af.z);
            const unsigned long long a3 = dupf(af.w);
            fma2(acc[0][0], a0, bb.x); fma2(acc[0][1], a0, bb.y);
            fma2(acc[1][0], a1, bb.x); fma2(acc[1][1], a1, bb.y);
            fma2(acc[2][0], a2, bb.x); fma2(acc[2][1], a2, bb.y);
            fma2(acc[3][0], a3, bb.x); fma2(acc[3][1], a3, bb.y);
        }
    }
#undef LOAD_CHUNK
    // epilogue
    const int m0 = (lane & 7) * 4;
#pragma unroll
    for (int i = 0; i < 4; i++) {
        int m = m0 + i;
#pragma unroll
        for (int j = 0; j < 2; j++) {
            float2 v = unpk(acc[i][j]);
            int n = wn0 + nloc + 2*j;
            if (atomic) {
                if (n   < Nw) atomicAdd(&outp[(size_t)m*ldo + n],   v.x);
                if (n+1 < Nw) atomicAdd(&outp[(size_t)m*ldo + n+1], v.y);
            } else {
                outp[(size_t)m*ldo + n]   = v.x + bias[n];
                outp[(size_t)m*ldo + n+1] = v.y + bias[n+1];
            }
        }
    }
}

// ---------------- standalone GEMM (KV init + batched decode) ----------------
__global__ void __launch_bounds__(256) gemm_std(
    const float* __restrict__ A, const float* __restrict__ W,
    const float* __restrict__ bias, float* __restrict__ out,
    int lda, int ldw, int ldo, int K)
{
    __shared__ SMg sm;
    tile_mm(A + (size_t)blockIdx.y*32*lda, nullptr, lda,
            W, ldw, false, blockIdx.x*128, 1 << 30,
            0, K, out + (size_t)blockIdx.y*32*ldo, ldo, bias, false, &sm);
}

// ---------------- persistent 64-step kernel ----------------
__global__ void __launch_bounds__(256, 1) step_all_k(
    const int* __restrict__ tokens, const float* __restrict__ emb,
    const float* __restrict__ lg, const float* __restrict__ lb,
    const float* __restrict__ Wq, const float* __restrict__ bq,
    const float* __restrict__ Wk, const float* __restrict__ bk,
    const float* __restrict__ Wv, const float* __restrict__ bv,
    const float* __restrict__ Wo, const float* __restrict__ bo,
    const float* __restrict__ W_ih, const float* __restrict__ b_ih,
    const float* __restrict__ W_hh, const float* __restrict__ b_hh)
{
    __shared__ SMU smu;
    SMg* sm = &smu.g;
    const int bid = blockIdx.x, tid = threadIdx.x;

    const unsigned ebase = *(volatile unsigned*)&g_be;
    unsigned nb_ = 0;
#define GB() do { nb_++; gbar(ebase + nb_); } while (0)

    for (int t = 0; t < T_STEPS; t++) {
        const int slot = t % MEM_;
        // ======== P1: embed+LN (0-31) | q=bq (32-63) | scores=0 (64-95) | att=0 (96-127)
        if (bid < 32) {
            const int b = bid;
            const int tok = tokens[t*B_ + b];
            const float* __restrict__ row = emb + (size_t)tok * D_;
            float v[4]; float s = 0.f;
#pragma unroll
            for (int i = 0; i < 4; i++) { v[i] = row[tid + i*256]; s += v[i]; }
            smu.red[tid] = s; __syncthreads();
            for (int o = 128; o > 0; o >>= 1) { if (tid < o) smu.red[tid] += smu.red[tid+o]; __syncthreads(); }
            const float mu = smu.red[0] * (1.f/D_);
            __syncthreads();
            s = 0.f;
#pragma unroll
            for (int i = 0; i < 4; i++) { float d = v[i]-mu; s += d*d; }
            smu.red[tid] = s; __syncthreads();
            for (int o = 128; o > 0; o >>= 1) { if (tid < o) smu.red[tid] += smu.red[tid+o]; __syncthreads(); }
            const float inv = 1.f / (sqrtf(smu.red[0] / (float)(D_-1)) + EPS_);
            __syncthreads();
#pragma unroll
            for (int i = 0; i < 4; i++) {
                int d = tid + i*256;
                g_e[(size_t)b*D_ + d] = v[i];
                g_eln[(size_t)b*D_ + d] = lg[d]*(v[i]-mu)*inv + lb[d];
            }
        } else if (bid < 64) {
            int base = (bid-32)*256 + tid;
#pragma unroll
            for (int s = 0; s < 4; s++) { int i = base + s*8192; g_q[i] = bq[i & 1023]; }
        } else if (bid < 96) {
            int base = (bid-64)*256 + tid;
            for (int s = 0; s < 9; s++) { int i = base + s*8192; if (i < HEADS_*B_*MB) g_scores[i] = 0.f; }
        } else {
            int base = (bid-96)*256 + tid;
#pragma unroll
            for (int s = 0; s < 4; s++) { int i = base + s*8192; g_att[i] = 0.f; }
        }
        GB();
        // ======== P2: q jobs (0-31) | g_ha = e + bo (32-63)
        if (bid < 32) {
            int tile = bid & 7, split = bid >> 3;
            tile_mm(g_eln, nullptr, D_, Wq, D_, false, tile*128, D_,
                    split*256, split*256+256, g_q, D_, nullptr, true, sm);
        } else if (bid < 64) {
            int base = (bid-32)*256 + tid;
#pragma unroll
            for (int s = 0; s < 4; s++) { int i = base + s*8192; g_ha[i] = g_e[i] + bo[i & 1023]; }
        }
        GB();
        // ======== P3: scores jobs (36): scores[h][b][m] += q_h[b,:] . KC_h[m,:]
        if (bid < 36) {
            int tile = bid % 9, rest = bid / 9;
            int h = rest >> 1, split = rest & 1;
            tile_mm(g_q + h*DK_, nullptr, D_, g_KC + h*DK_, D_, false, tile*128, MB,
                    split*256, split*256+256,
                    g_scores + (size_t)h*B_*MB, MB, nullptr, true, sm);
        }
        GB();
        // ======== P4: softmax over memory (64 rows)
        if (bid < HEADS_*B_) {
            const float* __restrict__ s = g_scores + (size_t)bid * MB;
            float* __restrict__ w = g_attnw + (size_t)bid * MB;
            float mx = -1e30f;
            for (int i = tid; i < MB; i += 256) mx = fmaxf(mx, s[i]);
            smu.red[tid] = mx; __syncthreads();
            for (int o = 128; o > 0; o >>= 1) { if (tid < o) smu.red[tid] = fmaxf(smu.red[tid], smu.red[tid+o]); __syncthreads(); }
            const float m2 = smu.red[0] * SCALE_;
            __syncthreads();
            float sum = 0.f;
            for (int i = tid; i < MB; i += 256) { float e = expf(fmaf(s[i], SCALE_, -m2)); w[i] = e; sum += e; }
            smu.red[tid] = sum; __syncthreads();
            for (int o = 128; o > 0; o >>= 1) { if (tid < o) smu.red[tid] += smu.red[tid+o]; __syncthreads(); }
            const float inv = 1.f / smu.red[0];
            __syncthreads();
            for (int i = tid; i < MB; i += 256) w[i] *= inv;
        }
        GB();
        // ======== P5: att jobs (32): att[b, h*DK+n] += attnw_h[b,:] . VC[:, h*DK+n]
        if (bid < 32) {
            static const int kr[5] = {0, 288, 576, 864, 1120};
            int h = bid >> 4, r = bid & 15;
            int tile = r & 3, split = r >> 2;
            tile_mm(g_attnw + (size_t)h*B_*MB, nullptr, MB, g_VC + h*DK_, D_, true,
                    tile*128, DK_, kr[split], kr[split+1],
                    g_att + h*DK_, D_, nullptr, true, sm);
        }
        GB();
        // ======== P6: o jobs (0-31) into g_ha | gates0 = bias (64-95)
        if (bid < 32) {
            int tile = bid & 7, split = bid >> 3;
            tile_mm(g_att, nullptr, D_, Wo, D_, false, tile*128, D_,
                    split*256, split*256+256, g_ha, D_, nullptr, true, sm);
        } else if (bid >= 64 && bid < 96) {
            int base = (bid-64)*256 + tid;
#pragma unroll
            for (int s = 0; s < 16; s++) {
                int i = base + s*8192;
                g_gates[i] = b_ih[i & 4095] + b_hh[i & 4095];
            }
        }
        GB();
        // ======== P7: gates L0 jobs (128): e@Wih0^T + (ha+h0)@Whh0^T
        {
            int tile = bid & 31, split = bid >> 5;
            if (split < 2)
                tile_mm(g_e, nullptr, D_, W_ih, D_, false, tile*128, 4*D_,
                        split*512, split*512+512, g_gates, 4*D_, nullptr, true, sm);
            else
                tile_mm(g_ha, g_h, D_, W_hh, D_, false, tile*128, 4*D_,
                        (split-2)*512, (split-2)*512+512, g_gates, 4*D_, nullptr, true, sm);
        }
        GB();
        // ======== P8: pointwise L0 + init gates2 bias + init KV slot bias
        {
            const int idx = bid*256 + tid;
            const int b = idx >> 10, d = idx & 1023;
            const float* __restrict__ gr = g_gates + (size_t)b*4*D_;
            const float ig = gr[d], fg = gr[D_+d], gg = gr[2*D_+d], og = gr[3*D_+d];
            const float cn = sigf(fg)*g_c[idx] + sigf(ig)*tanhf(gg);
            const float hn = sigf(og)*tanhf(cn);
            g_h[idx] = hn; g_c[idx] = cn;
            g_histh[((size_t)t*L_)*BD + idx] = hn;
            g_histc[((size_t)t*L_)*BD + idx] = cn;
#pragma unroll
            for (int s = 0; s < 4; s++) {
                int i = idx + s*32768;
                g_gates2[i] = b_ih[4*D_ + (i & 4095)] + b_hh[4*D_ + (i & 4095)];
            }
            g_KC[(size_t)slot*BD + idx] = bk[d];
            g_VC[(size_t)slot*BD + idx] = bv[d];
        }
        GB();
        // ======== P9: gates L1 jobs (128): h0new@Wih1^T + (ha+h1)@Whh1^T
        {
            int tile = bid & 31, split = bid >> 5;
            if (split < 2)
                tile_mm(g_h, nullptr, D_, W_ih + (size_t)4*D_*D_, D_, false, tile*128, 4*D_,
                        split*512, split*512+512, g_gates2, 4*D_, nullptr, true, sm);
            else
                tile_mm(g_ha, g_h + BD, D_, W_hh + (size_t)4*D_*D_, D_, false, tile*128, 4*D_,
                        (split-2)*512, (split-2)*512+512, g_gates2, 4*D_, nullptr, true, sm);
        }
        GB();
        // ======== P10: pointwise L1 (+X history) | KV jobs (0-31)
        {
            const int idx = bid*256 + tid;
            const int b = idx >> 10, d = idx & 1023;
            const float* __restrict__ gr = g_gates2 + (size_t)b*4*D_;
            const float ig = gr[d], fg = gr[D_+d], gg = gr[2*D_+d], og = gr[3*D_+d];
            const float cn = sigf(fg)*g_c[BD + idx] + sigf(ig)*tanhf(gg);
            const float hn = sigf(og)*tanhf(cn);
            g_h[BD + idx] = hn; g_c[BD + idx] = cn;
            g_histh[((size_t)t*L_ + 1)*BD + idx] = hn;
            g_histc[((size_t)t*L_ + 1)*BD + idx] = cn;
            g_X[(size_t)t*BD + idx] = hn;
        }
        __syncthreads();
        if (bid < 32) {
            bool isK = bid < 16;
            int r = bid & 15, tile = r & 7, split = r >> 3;
            tile_mm(g_h, nullptr, D_, isK ? Wk : Wv, D_, false, tile*128, D_,
                    split*512, split*512+512,
                    (isK ? g_KC : g_VC) + (size_t)slot*BD, D_, nullptr, true, sm);
        }
        GB();
    }
#undef GB
}

// ---------------- final state / memory gather ----------------
__global__ void __launch_bounds__(256) finalize_k(float* __restrict__ out)
{
    const int idx = blockIdx.x*256 + threadIdx.x;
    const int l = idx / (MEM_*BD);
    const int r = idx % (MEM_*BD);
    const int m = r / BD, j = r % BD;
    const size_t src = ((size_t)(T_STEPS - MEM_ + m)*L_ + l)*BD + j;
    out[OFF_H + idx] = g_histh[src];
    out[OFF_C + idx] = g_histc[src];
    if (idx < L_*BD) {
        out[OFF_h + idx] = g_h[idx];
        out[OFF_c + idx] = g_c[idx];
    }
}

// ---------------- host ----------------
extern "C" void kernel_launch(void* const* d_in, const int* in_sizes, int n_in,
                              void* d_out, int out_size)
{
    const int*   tokens = (const int*)  d_in[0];
    const float* emb    = (const float*)d_in[1];
    const float* ln_g   = (const float*)d_in[2];
    const float* ln_b   = (const float*)d_in[3];
    const float* Wq     = (const float*)d_in[4];
    const float* bq     = (const float*)d_in[5];
    const float* Wk     = (const float*)d_in[6];
    const float* bk     = (const float*)d_in[7];
    const float* Wv     = (const float*)d_in[8];
    const float* bv     = (const float*)d_in[9];
    const float* Wo     = (const float*)d_in[10];
    const float* bo     = (const float*)d_in[11];
    const float* W_ih   = (const float*)d_in[12];
    const float* b_ih   = (const float*)d_in[13];
    const float* W_hh   = (const float*)d_in[14];
    const float* b_hh   = (const float*)d_in[15];
    const float* dec_W  = (const float*)d_in[16];
    const float* dec_b  = (const float*)d_in[17];
    const float* h0     = (const float*)d_in[18];
    const float* c0     = (const float*)d_in[19];
    const float* H0     = (const float*)d_in[20];
    // d_in[21] = C0: unobservable (T >= MEM rolls it out)
    float* out = (float*)d_out;

    float *ph, *pc, *pKC, *pVC, *pX;
    cudaGetSymbolAddress((void**)&ph,  g_h);
    cudaGetSymbolAddress((void**)&pc,  g_c);
    cudaGetSymbolAddress((void**)&pKC, g_KC);
    cudaGetSymbolAddress((void**)&pVC, g_VC);
    cudaGetSymbolAddress((void**)&pX,  g_X);

    cudaMemcpyAsync(ph, h0, (size_t)L_*BD*sizeof(float), cudaMemcpyDeviceToDevice);
    cudaMemcpyAsync(pc, c0, (size_t)L_*BD*sizeof(float), cudaMemcpyDeviceToDevice);

    // initial K/V cache from H0 layer 0: rows m*B+b of [MEM*B, D]
    gemm_std<<<dim3(8, 35), 256>>>(H0, Wk, bk, pKC, D_, D_, D_, D_);
    gemm_std<<<dim3(8, 35), 256>>>(H0, Wv, bv, pVC, D_, D_, D_, D_);

    // persistent 64-step kernel
    step_all_k<<<GRID, 256>>>(tokens, emb, ln_g, ln_b, Wq, bq, Wk, bk, Wv, bv,
                              Wo, bo, W_ih, b_ih, W_hh, b_hh);

    // batched decode: [2048, 32000] = X @ dec_W^T + dec_b
    gemm_std<<<dim3(NTOK_/128, T_STEPS*B_/32), 256>>>(pX, dec_W, dec_b, out,
                                                      D_, D_, NTOK_, D_);

    finalize_k<<<(L_*MEM_*BD)/256, 256>>>(out);
}